// round 4
// baseline (speedup 1.0000x reference)
#include <cuda_runtime.h>

// LUT-tree conv: B=8, C=64, H=W=32, O=32, Q=8, K=3.
// Per (b,o) block: precompute sigmoid(x) for the 8 selected channels into SMEM
// (34x34 window with halo=0.5 == sigmoid(conv zero-pad)), then each thread
// evaluates the 4-level LUT tree for 4 consecutive wo pixels.

#define NHS 35            // smem row stride (odd -> conflict-free)
#define NQS (34 * NHS)    // per-channel smem plane (34 rows incl. halo)

__device__ __forceinline__ float fsig(float x) {
    // sigmoid via ex2.approx + rcp.approx (~1e-6 rel err, 2 MUFU)
    float e, r;
    asm("ex2.approx.f32 %0, %1;" : "=f"(e) : "f"(x * -1.4426950408889634f));
    asm("rcp.approx.f32 %0, %1;" : "=f"(r) : "f"(1.0f + e));
    return r;
}

__device__ __forceinline__ float flerp(float lo, float hi, float t) {
    return fmaf(t, hi - lo, lo);
}

// Multilinear interp over 16 corners; bit i of corner index == input i.
__device__ __forceinline__ float lut4(const float w[16],
                                      float x0, float x1, float x2, float x3) {
    float a0 = flerp(w[0],  w[1],  x0);
    float a1 = flerp(w[2],  w[3],  x0);
    float a2 = flerp(w[4],  w[5],  x0);
    float a3 = flerp(w[6],  w[7],  x0);
    float a4 = flerp(w[8],  w[9],  x0);
    float a5 = flerp(w[10], w[11], x0);
    float a6 = flerp(w[12], w[13], x0);
    float a7 = flerp(w[14], w[15], x0);
    float b0 = flerp(a0, a1, x1);
    float b1 = flerp(a2, a3, x1);
    float b2 = flerp(a4, a5, x1);
    float b3 = flerp(a6, a7, x1);
    float c0 = flerp(b0, b1, x2);
    float c1 = flerp(b2, b3, x2);
    return flerp(c0, c1, x3);
}

// Feature j (0..71) -> smem offset. j = q*9 + kh*3 + kw.
__device__ __forceinline__ int foff(int j) {
    int q = j / 9, r = j % 9;
    return q * NQS + (r / 3) * NHS + (r % 3);
}

__global__ __launch_bounds__(256) void lut_tree_kernel(
    const float* __restrict__ x,
    const float* __restrict__ w0, const float* __restrict__ w1,
    const float* __restrict__ w2, const float* __restrict__ w3,
    const int* __restrict__ ci, float* __restrict__ out)
{
    __shared__ float S[8 * NQS];   // sigmoided selected channels + halo
    __shared__ float W[416];       // w0(288) | w1(80) | w2(32) | w3(16)

    const int o = blockIdx.x;      // 0..31
    const int b = blockIdx.y;      // 0..7
    const int tid = threadIdx.x;

    // Stage weights for this output unit into SMEM.
    for (int i = tid; i < 416; i += 256) {
        float v;
        if (i < 288)      v = w0[o * 288 + i];
        else if (i < 368) v = w1[o * 80 + (i - 288)];
        else if (i < 400) v = w2[o * 32 + (i - 368)];
        else              v = w3[o * 16 + (i - 400)];
        W[i] = v;
    }
    // Halo (and everything) = sigmoid(0) = 0.5.
    for (int i = tid; i < 8 * NQS; i += 256) S[i] = 0.5f;
    __syncthreads();

    // Fill interior: sigmoid of the 8 selected channels.
    #pragma unroll
    for (int q = 0; q < 8; q++) {
        const int ch = ci[o * 8 + q];
        const float* xc = x + ((size_t)(b * 64 + ch)) * 1024;
        for (int pix = tid; pix < 1024; pix += 256) {
            int hh = pix >> 5, ww = pix & 31;
            S[q * NQS + (hh + 1) * NHS + (ww + 1)] = fsig(xc[pix]);
        }
    }
    __syncthreads();

    // Each thread: row ty, 4 consecutive columns starting at wb.
    const int ty = tid >> 3;
    const int wb = (tid & 7) << 2;
    const int base = ty * NHS + wb;

    float h1s[4][5];   // sigmoided level-1 outputs per pixel

    // Level 0 (18 LUTs) streamed into level 1 (5 LUTs), 4 pixels at a time.
    #pragma unroll
    for (int g = 0; g < 5; g++) {
        float in[4][4];  // [level1 input k][pixel]
        #pragma unroll
        for (int k = 0; k < 4; k++) {
            const int l = g * 4 + k;
            if (l < 18) {
                float wr[16];
                #pragma unroll
                for (int c = 0; c < 16; c++) wr[c] = W[l * 16 + c];
                #pragma unroll
                for (int p = 0; p < 4; p++) {
                    float f0 = S[base + foff(l * 4 + 0) + p];
                    float f1 = S[base + foff(l * 4 + 1) + p];
                    float f2 = S[base + foff(l * 4 + 2) + p];
                    float f3 = S[base + foff(l * 4 + 3) + p];
                    in[k][p] = fsig(lut4(wr, f0, f1, f2, f3));
                }
            } else {
                #pragma unroll
                for (int p = 0; p < 4; p++) in[k][p] = 0.5f;  // post-sigmoid pad
            }
        }
        float wr[16];
        #pragma unroll
        for (int c = 0; c < 16; c++) wr[c] = W[288 + g * 16 + c];
        #pragma unroll
        for (int p = 0; p < 4; p++)
            h1s[p][g] = fsig(lut4(wr, in[0][p], in[1][p], in[2][p], in[3][p]));
    }

    // Level 2: LUT0 <- h1[0..3]; LUT1 <- h1[4], pad, pad, pad.
    float h2s[4][2];
    {
        float wr[16];
        #pragma unroll
        for (int c = 0; c < 16; c++) wr[c] = W[368 + c];
        #pragma unroll
        for (int p = 0; p < 4; p++)
            h2s[p][0] = fsig(lut4(wr, h1s[p][0], h1s[p][1], h1s[p][2], h1s[p][3]));
    }
    {
        float wr[16];
        #pragma unroll
        for (int c = 0; c < 16; c++) wr[c] = W[384 + c];
        #pragma unroll
        for (int p = 0; p < 4; p++)
            h2s[p][1] = fsig(lut4(wr, h1s[p][4], 0.5f, 0.5f, 0.5f));
    }

    // Level 3 (no sigmoid): inputs h2[0], h2[1], pad, pad.
    float4 ov;
    {
        float wr[16];
        #pragma unroll
        for (int c = 0; c < 16; c++) wr[c] = W[400 + c];
        float r0 = lut4(wr, h2s[0][0], h2s[0][1], 0.5f, 0.5f);
        float r1 = lut4(wr, h2s[1][0], h2s[1][1], 0.5f, 0.5f);
        float r2 = lut4(wr, h2s[2][0], h2s[2][1], 0.5f, 0.5f);
        float r3 = lut4(wr, h2s[3][0], h2s[3][1], 0.5f, 0.5f);
        ov = make_float4(r0, r1, r2, r3);
    }

    // out[b][o][ty][wb..wb+3], 16B-aligned.
    *reinterpret_cast<float4*>(&out[(((b * 32 + o) * 32 + ty) * 32) + wb]) = ov;
}

extern "C" void kernel_launch(void* const* d_in, const int* in_sizes, int n_in,
                              void* d_out, int out_size) {
    const float* x  = (const float*)d_in[0];
    const float* w0 = (const float*)d_in[1];
    const float* w1 = (const float*)d_in[2];
    const float* w2 = (const float*)d_in[3];
    const float* w3 = (const float*)d_in[4];
    const int*   ci = (const int*)d_in[5];
    dim3 grid(32, 8);   // (O, B)
    lut_tree_kernel<<<grid, 256>>>(x, w0, w1, w2, w3, ci, (float*)d_out);
}